// round 16
// baseline (speedup 1.0000x reference)
#include <cuda_runtime.h>
#include <cuda_fp16.h>
#include <cstdint>

// ---------------------------------------------------------------------------
// PatchMerging (B=64, H=W=28, DIM=384):
//   1) fused prep: wconv (w_reduction -> fp16) + cls GEMM
//   2) gather + LayerNorm -> fp16 (2 rows/block)
//   3) mma.sync m16n8k16 fp16 GEMM, tile 128x128x32, 256 threads
//      (16 warps 4Mx4N, warp tile 32x32), 3-stage cp.async, seg-XOR swizzle,
//      3 CTAs/SM (three independent barrier domains per SM).
// ---------------------------------------------------------------------------

#define BATCH   64
#define LSEQ    785
#define DIM     384
#define FDIM    1536
#define ODIM    768
#define NPOS    196
#define MROWS   (BATCH * NPOS)   // 12544
#define OUTROWS 197

__device__ __half g_mbuf[(size_t)MROWS * FDIM];
__device__ __half g_wred[(size_t)ODIM * FDIM];

// ------------------------------ helpers -----------------------------------
__device__ __forceinline__ uint32_t smem_u32(const void* p) {
    uint32_t a;
    asm("{ .reg .u64 t; cvta.to.shared.u64 t, %1; cvt.u32.u64 %0, t; }"
        : "=r"(a) : "l"(p));
    return a;
}
#define CP_ASYNC16(saddr, gptr) \
    asm volatile("cp.async.cg.shared.global [%0], [%1], 16;" :: "r"(saddr), "l"(gptr))
#define CP_COMMIT() asm volatile("cp.async.commit_group;" ::: "memory")
template <int N>
__device__ __forceinline__ void cp_wait() {
    asm volatile("cp.async.wait_group %0;" :: "n"(N) : "memory");
}

__device__ __forceinline__ void mma_f16(float* d, uint32_t a0, uint32_t a1,
                                        uint32_t a2, uint32_t a3,
                                        uint32_t b0, uint32_t b1) {
    asm volatile(
        "mma.sync.aligned.m16n8k16.row.col.f32.f16.f16.f32 "
        "{%0,%1,%2,%3}, {%4,%5,%6,%7}, {%8,%9}, {%0,%1,%2,%3};"
        : "+f"(d[0]), "+f"(d[1]), "+f"(d[2]), "+f"(d[3])
        : "r"(a0), "r"(a1), "r"(a2), "r"(a3), "r"(b0), "r"(b1));
}

// ---------------------------------------------------------------------------
// Kernel 1: gather + LayerNorm, 2 rows per 256-thread block, fp16 out
// ---------------------------------------------------------------------------
__global__ __launch_bounds__(256) void ln_gather_kernel(
    const float* __restrict__ x,
    const float* __restrict__ gamma,
    const float* __restrict__ beta,
    __half* __restrict__ mbuf)
{
    const int tid  = threadIdx.x;
    const int half = tid >> 7;
    const int t    = tid & 127;
    const int r    = blockIdx.x * 2 + half;
    const int b    = r / NPOS;
    const int n    = r - b * NPOS;
    const int h2   = n / 14;
    const int w2   = n - h2 * 14;

    const float* xb = x + (size_t)b * LSEQ * DIM;
    const int rowbase = 1 + (2 * h2) * 28 + 2 * w2;

    float4 v[3];
    float s = 0.f, ss = 0.f;
#pragma unroll
    for (int i = 0; i < 3; i++) {
        const int f4 = t + i * 128;
        const int f  = f4 * 4;
        const int q  = f / DIM;
        const int c  = f - q * DIM;
        const int drow = q & 1;
        const int dcol = q >> 1;
        const int L = rowbase + drow * 28 + dcol;
        const float4 val = *(const float4*)(xb + (size_t)L * DIM + c);
        v[i] = val;
        s  += val.x + val.y + val.z + val.w;
        ss += val.x * val.x + val.y * val.y + val.z * val.z + val.w * val.w;
    }

    __shared__ float red_s[2][4], red_ss[2][4];
#pragma unroll
    for (int off = 16; off > 0; off >>= 1) {
        s  += __shfl_xor_sync(0xFFFFFFFFu, s,  off);
        ss += __shfl_xor_sync(0xFFFFFFFFu, ss, off);
    }
    const int warp4 = (t >> 5);
    const int lane  = t & 31;
    if (lane == 0) { red_s[half][warp4] = s; red_ss[half][warp4] = ss; }
    __syncthreads();
    const float sum  = red_s[half][0] + red_s[half][1] + red_s[half][2] + red_s[half][3];
    const float sums = red_ss[half][0] + red_ss[half][1] + red_ss[half][2] + red_ss[half][3];

    const float inv  = 1.0f / (float)FDIM;
    const float mean = sum * inv;
    const float var  = sums * inv - mean * mean;
    const float rstd = rsqrtf(var + 1e-5f);

    __half* mrow = mbuf + (size_t)r * FDIM;
#pragma unroll
    for (int i = 0; i < 3; i++) {
        const int f4 = t + i * 128;
        const int f  = f4 * 4;
        const float4 g = *(const float4*)(gamma + f);
        const float4 be = *(const float4*)(beta + f);
        const __half2 h01 = __floats2half2_rn((v[i].x - mean) * rstd * g.x + be.x,
                                              (v[i].y - mean) * rstd * g.y + be.y);
        const __half2 h23 = __floats2half2_rn((v[i].z - mean) * rstd * g.z + be.z,
                                              (v[i].w - mean) * rstd * g.w + be.w);
        uint2 pk;
        pk.x = *(const uint32_t*)&h01;
        pk.y = *(const uint32_t*)&h23;
        *(uint2*)(mrow + f) = pk;
    }
}

// ---------------------------------------------------------------------------
// Kernel 1b (fused): wconv + cls.
// ---------------------------------------------------------------------------
#define WCONV_BLOCKS ((ODIM * FDIM) / 1024)        // 1152
#define CLS_BLOCKS   ((BATCH * ODIM / 4) / 8)      // 1536

__global__ __launch_bounds__(256) void prep_kernel(
    const float* __restrict__ w_red,
    __half* __restrict__ wred_h,
    const float* __restrict__ x,
    const float* __restrict__ wc,
    float* __restrict__ out)
{
    if (blockIdx.x < WCONV_BLOCKS) {
        const int i = (blockIdx.x * 256 + threadIdx.x) * 4;
        const float4 v = *(const float4*)(w_red + i);
        const __half2 h01 = __floats2half2_rn(v.x, v.y);
        const __half2 h23 = __floats2half2_rn(v.z, v.w);
        uint2 pk;
        pk.x = *(const uint32_t*)&h01;
        pk.y = *(const uint32_t*)&h23;
        *(uint2*)(wred_h + i) = pk;
        return;
    }

    const int cb    = blockIdx.x - WCONV_BLOCKS;
    const int warp  = threadIdx.x >> 5;
    const int lane  = threadIdx.x & 31;
    const int group = cb * 8 + warp;
    const int b     = group / (ODIM / 4);
    const int o0    = (group - b * (ODIM / 4)) * 4;

    const float4* xrow = (const float4*)(x + (size_t)b * LSEQ * DIM);
    float4 xv[3];
#pragma unroll
    for (int j = 0; j < 3; j++) xv[j] = xrow[lane + 32 * j];

    float s[4];
#pragma unroll
    for (int k = 0; k < 4; k++) {
        const float4* wrow = (const float4*)(wc + (size_t)(o0 + k) * DIM);
        float acc = 0.f;
#pragma unroll
        for (int j = 0; j < 3; j++) {
            const float4 wv = wrow[lane + 32 * j];
            acc += wv.x * xv[j].x + wv.y * xv[j].y + wv.z * xv[j].z + wv.w * xv[j].w;
        }
        s[k] = acc;
    }
#pragma unroll
    for (int k = 0; k < 4; k++) {
#pragma unroll
        for (int off = 16; off > 0; off >>= 1)
            s[k] += __shfl_xor_sync(0xFFFFFFFFu, s[k], off);
    }
    if (lane == 0) {
        float* op = out + (size_t)b * OUTROWS * ODIM + o0;
        op[0] = s[0]; op[1] = s[1]; op[2] = s[2]; op[3] = s[3];
    }
}

// ---------------------------------------------------------------------------
// Kernel 2: fp16 mma.sync GEMM, 128x128x32, 256 thr (16 warps 4Mx4N,
// warp tile 32x32), 3-stage cp.async, 3 CTAs/SM.
// Smem row = 32 halves (64B = 4 segs of 16B). Seg s of row r stored at
// phys = s ^ (r & 3). Fragment LDS.128 phases (2 rows x 4 quarters) then
// cover 8 distinct 16B groups -> conflict-free.
// k32 grouping: quarter cl owns halves 8cl..8cl+7; mma#1 .x/.y, mma#2 .z/.w.
// ---------------------------------------------------------------------------
#define BM 128
#define BN 128
#define BK 32
#define ROWH 32                              // halves per smem row (64B)
#define A_TILE_B (BM * ROWH * 2)             // 8192 bytes
#define B_TILE_B (BN * ROWH * 2)             // 8192
#define STAGE_B (A_TILE_B + B_TILE_B)        // 16384
#define NSTAGE 3
#define NCHUNK (FDIM / BK)                   // 48
#define GEMM_SMEM (NSTAGE * STAGE_B)         // 49152

__global__ __launch_bounds__(256, 3) void gemm_mma_kernel(
    const __half* __restrict__ A,
    const __half* __restrict__ W,
    float* __restrict__ out)
{
    extern __shared__ __align__(16) char smc[];
    __half* sm = (__half*)smc;

    const int tid  = threadIdx.x;
    const int lane = tid & 31;
    const int wid  = tid >> 5;               // 0..15? no: 256 thr = 8 warps!
    // NOTE: 256 threads = 8 warps. Use 8 warps as 4M x 2N, warp tile 32x64?
    // -- corrected layout below: 16 warps needs 512 threads. We use 8 warps
    //    as 4M x 2N with warp tile 32x64: acc[2][8][4] = 64 regs.
    const int m0 = blockIdx.y * BM;
    const int n0 = blockIdx.x * BN;
    const int wm = (wid >> 1) * 32;          // 0,32,64,96
    const int wn = (wid & 1) * 64;           // 0,64

    const __half* gA = A + (size_t)m0 * FDIM;
    const __half* gB = W + (size_t)n0 * FDIM;

    const uint32_t smbase = smem_u32(sm);

    // loader: thread t -> row t>>1 (0..127), segs (t&1)*2 .. +1 (16B each)
    const int lrow = tid >> 1;
    const int lseg = (tid & 1) * 2;
    const uint32_t lx = (uint32_t)(lrow & 3);

    auto load_chunk = [&](int chunk, int stage) {
        const uint32_t base = smbase + (uint32_t)stage * STAGE_B;
        const int koff = chunk * BK;
        const __half* pA = gA + (size_t)lrow * FDIM + koff;
        const uint32_t sA = base + (uint32_t)lrow * (ROWH * 2);
#pragma unroll
        for (int s = 0; s < 2; s++) {
            const uint32_t phys = ((uint32_t)(lseg + s) ^ lx) * 16;
            CP_ASYNC16(sA + phys, pA + (lseg + s) * 8);
        }
        const __half* pB = gB + (size_t)lrow * FDIM + koff;
        const uint32_t sB = base + A_TILE_B + (uint32_t)lrow * (ROWH * 2);
#pragma unroll
        for (int s = 0; s < 2; s++) {
            const uint32_t phys = ((uint32_t)(lseg + s) ^ lx) * 16;
            CP_ASYNC16(sB + phys, pB + (lseg + s) * 8);
        }
        CP_COMMIT();
    };

    float acc[2][8][4];
#pragma unroll
    for (int mt = 0; mt < 2; mt++)
#pragma unroll
        for (int nt = 0; nt < 8; nt++)
#pragma unroll
            for (int j = 0; j < 4; j++) acc[mt][nt][j] = 0.f;

    load_chunk(0, 0);
    load_chunk(1, 1);
    cp_wait<1>();
    __syncthreads();

    const int g2 = lane >> 2;                // 0..7
    const int cl = lane & 3;                 // k-quarter (owns 8 halves)

    for (int i = 0; i < NCHUNK; i++) {
        const int ld = i + 2;
        if (ld < NCHUNK) load_chunk(ld, ld % NSTAGE);

        const int s = i % NSTAGE;
        const __half* As = sm + (size_t)s * (STAGE_B / 2);
        const __half* Bs = As + A_TILE_B / 2;

        uint4 aLo[2], aHi[2];
#pragma unroll
        for (int mt = 0; mt < 2; mt++) {
            const int r = wm + mt * 16 + g2;
            aLo[mt] = *(const uint4*)(As + r * ROWH + ((cl ^ (r & 3)) * 8));
            const int r2 = r + 8;
            aHi[mt] = *(const uint4*)(As + r2 * ROWH + ((cl ^ (r2 & 3)) * 8));
        }
        uint4 bv[8];
#pragma unroll
        for (int nt = 0; nt < 8; nt++) {
            const int n = wn + nt * 8 + g2;
            bv[nt] = *(const uint4*)(Bs + n * ROWH + ((cl ^ (n & 3)) * 8));
        }
#pragma unroll
        for (int nt = 0; nt < 8; nt++)
#pragma unroll
            for (int mt = 0; mt < 2; mt++)
                mma_f16(acc[mt][nt], aLo[mt].x, aHi[mt].x, aLo[mt].y, aHi[mt].y,
                        bv[nt].x, bv[nt].y);
#pragma unroll
        for (int nt = 0; nt < 8; nt++)
#pragma unroll
            for (int mt = 0; mt < 2; mt++)
                mma_f16(acc[mt][nt], aLo[mt].z, aHi[mt].z, aLo[mt].w, aHi[mt].w,
                        bv[nt].z, bv[nt].w);

        if (ld < NCHUNK) { cp_wait<1>(); } else { cp_wait<0>(); }
        __syncthreads();
    }

    // epilogue: write with batch/row remap
    const int c2 = 2 * (lane & 3);
#pragma unroll
    for (int mt = 0; mt < 2; mt++) {
        const int mA = m0 + wm + mt * 16 + g2;
#pragma unroll
        for (int half = 0; half < 2; half++) {
            const int m  = mA + half * 8;
            const int b  = m / NPOS;
            const int nn = m - b * NPOS;
            float* orow = out + ((size_t)b * OUTROWS + 1 + nn) * ODIM + n0 + wn;
#pragma unroll
            for (int nt = 0; nt < 8; nt++) {
                float2 v;
                v.x = acc[mt][nt][2 * half + 0];
                v.y = acc[mt][nt][2 * half + 1];
                *(float2*)(orow + nt * 8 + c2) = v;
            }
        }
    }
}

// ---------------------------------------------------------------------------
extern "C" void kernel_launch(void* const* d_in, const int* in_sizes, int n_in,
                              void* d_out, int out_size)
{
    const float* x     = (const float*)d_in[0];
    const float* w_red = (const float*)d_in[1];
    const float* w_cvt = (const float*)d_in[2];
    const float* gamma = (const float*)d_in[3];
    const float* beta  = (const float*)d_in[4];
    float* out = (float*)d_out;

    __half* mbuf;
    __half* wred;
    cudaGetSymbolAddress((void**)&mbuf, g_mbuf);
    cudaGetSymbolAddress((void**)&wred, g_wred);

    cudaFuncSetAttribute(gemm_mma_kernel,
                         cudaFuncAttributeMaxDynamicSharedMemorySize, GEMM_SMEM);

    prep_kernel<<<WCONV_BLOCKS + CLS_BLOCKS, 256>>>(w_red, wred, x, w_cvt, out);
    ln_gather_kernel<<<MROWS / 2, 256>>>(x, gamma, beta, mbuf);
    gemm_mma_kernel<<<dim3(ODIM / BN, MROWS / BM), 256, GEMM_SMEM>>>(mbuf, wred, out);
}

// round 17
// speedup vs baseline: 2.6901x; 2.6901x over previous
#include <cuda_runtime.h>
#include <cuda_fp16.h>
#include <cstdint>

// ---------------------------------------------------------------------------
// PatchMerging (B=64, H=W=28, DIM=384):
//   1) ONE pre-kernel (block-range dispatch):
//        [0, 1152)    : w_reduction -> fp16
//        [1152, 2688) : cls GEMM (4 outputs/warp)
//        [2688, 8960) : gather + LayerNorm -> fp16 (2 rows/block)
//   2) mma.sync m16n8k16 fp16 GEMM, tile 128x128x64, 256 threads
//      (8 warps 2Mx4N, warp 64x32), 3-stage cp.async, XOR row-parity
//      swizzle, 2 CTAs/SM.   (proven R13/R15 core — do not touch)
// ---------------------------------------------------------------------------

#define BATCH   64
#define LSEQ    785
#define DIM     384
#define FDIM    1536
#define ODIM    768
#define NPOS    196
#define MROWS   (BATCH * NPOS)   // 12544
#define OUTROWS 197

__device__ __half g_mbuf[(size_t)MROWS * FDIM];
__device__ __half g_wred[(size_t)ODIM * FDIM];

// ------------------------------ helpers -----------------------------------
__device__ __forceinline__ uint32_t smem_u32(const void* p) {
    uint32_t a;
    asm("{ .reg .u64 t; cvta.to.shared.u64 t, %1; cvt.u32.u64 %0, t; }"
        : "=r"(a) : "l"(p));
    return a;
}
#define CP_ASYNC16(saddr, gptr) \
    asm volatile("cp.async.cg.shared.global [%0], [%1], 16;" :: "r"(saddr), "l"(gptr))
#define CP_COMMIT() asm volatile("cp.async.commit_group;" ::: "memory")
template <int N>
__device__ __forceinline__ void cp_wait() {
    asm volatile("cp.async.wait_group %0;" :: "n"(N) : "memory");
}

__device__ __forceinline__ void mma_f16(float* d, uint32_t a0, uint32_t a1,
                                        uint32_t a2, uint32_t a3,
                                        uint32_t b0, uint32_t b1) {
    asm volatile(
        "mma.sync.aligned.m16n8k16.row.col.f32.f16.f16.f32 "
        "{%0,%1,%2,%3}, {%4,%5,%6,%7}, {%8,%9}, {%0,%1,%2,%3};"
        : "+f"(d[0]), "+f"(d[1]), "+f"(d[2]), "+f"(d[3])
        : "r"(a0), "r"(a1), "r"(a2), "r"(a3), "r"(b0), "r"(b1));
}

// ---------------------------------------------------------------------------
// Pre-kernel: wconv + cls + LayerNorm-gather fused via block-range dispatch.
// ---------------------------------------------------------------------------
#define WCONV_BLOCKS ((ODIM * FDIM) / 1024)        // 1152
#define CLS_BLOCKS   ((BATCH * ODIM / 4) / 8)      // 1536
#define LN_BLOCKS    (MROWS / 2)                   // 6272
#define PRE_BLOCKS   (WCONV_BLOCKS + CLS_BLOCKS + LN_BLOCKS)

__global__ __launch_bounds__(256) void pre_kernel(
    const float* __restrict__ w_red,
    __half* __restrict__ wred_h,
    const float* __restrict__ x,
    const float* __restrict__ wc,
    const float* __restrict__ gamma,
    const float* __restrict__ beta,
    __half* __restrict__ mbuf,
    float* __restrict__ out)
{
    if (blockIdx.x < WCONV_BLOCKS) {
        // ---- w_reduction -> fp16 ----
        const int i = (blockIdx.x * 256 + threadIdx.x) * 4;
        const float4 v = *(const float4*)(w_red + i);
        const __half2 h01 = __floats2half2_rn(v.x, v.y);
        const __half2 h23 = __floats2half2_rn(v.z, v.w);
        uint2 pk;
        pk.x = *(const uint32_t*)&h01;
        pk.y = *(const uint32_t*)&h23;
        *(uint2*)(wred_h + i) = pk;
        return;
    }

    if (blockIdx.x < WCONV_BLOCKS + CLS_BLOCKS) {
        // ---- cls GEMM: warp computes 4 outputs of one batch row ----
        const int cb    = blockIdx.x - WCONV_BLOCKS;
        const int warp  = threadIdx.x >> 5;
        const int lane  = threadIdx.x & 31;
        const int group = cb * 8 + warp;
        const int b     = group / (ODIM / 4);
        const int o0    = (group - b * (ODIM / 4)) * 4;

        const float4* xrow = (const float4*)(x + (size_t)b * LSEQ * DIM);
        float4 xv[3];
#pragma unroll
        for (int j = 0; j < 3; j++) xv[j] = xrow[lane + 32 * j];

        float s[4];
#pragma unroll
        for (int k = 0; k < 4; k++) {
            const float4* wrow = (const float4*)(wc + (size_t)(o0 + k) * DIM);
            float acc = 0.f;
#pragma unroll
            for (int j = 0; j < 3; j++) {
                const float4 wv = wrow[lane + 32 * j];
                acc += wv.x * xv[j].x + wv.y * xv[j].y + wv.z * xv[j].z + wv.w * xv[j].w;
            }
            s[k] = acc;
        }
#pragma unroll
        for (int k = 0; k < 4; k++) {
#pragma unroll
            for (int off = 16; off > 0; off >>= 1)
                s[k] += __shfl_xor_sync(0xFFFFFFFFu, s[k], off);
        }
        if (lane == 0) {
            float* op = out + (size_t)b * OUTROWS * ODIM + o0;
            op[0] = s[0]; op[1] = s[1]; op[2] = s[2]; op[3] = s[3];
        }
        return;
    }

    // ---- gather + LayerNorm: 2 rows per block ----
    {
        const int lb   = blockIdx.x - WCONV_BLOCKS - CLS_BLOCKS;
        const int tid  = threadIdx.x;
        const int half = tid >> 7;
        const int t    = tid & 127;
        const int r    = lb * 2 + half;
        const int b    = r / NPOS;
        const int n    = r - b * NPOS;
        const int h2   = n / 14;
        const int w2   = n - h2 * 14;

        const float* xb = x + (size_t)b * LSEQ * DIM;
        const int rowbase = 1 + (2 * h2) * 28 + 2 * w2;

        float4 v[3];
        float s = 0.f, ss = 0.f;
#pragma unroll
        for (int i = 0; i < 3; i++) {
            const int f4 = t + i * 128;
            const int f  = f4 * 4;
            const int q  = f / DIM;
            const int c  = f - q * DIM;
            const int drow = q & 1;
            const int dcol = q >> 1;
            const int L = rowbase + drow * 28 + dcol;
            const float4 val = *(const float4*)(xb + (size_t)L * DIM + c);
            v[i] = val;
            s  += val.x + val.y + val.z + val.w;
            ss += val.x * val.x + val.y * val.y + val.z * val.z + val.w * val.w;
        }

        __shared__ float red_s[2][4], red_ss[2][4];
#pragma unroll
        for (int off = 16; off > 0; off >>= 1) {
            s  += __shfl_xor_sync(0xFFFFFFFFu, s,  off);
            ss += __shfl_xor_sync(0xFFFFFFFFu, ss, off);
        }
        const int warp4 = (t >> 5);
        const int lane  = t & 31;
        if (lane == 0) { red_s[half][warp4] = s; red_ss[half][warp4] = ss; }
        __syncthreads();
        const float sum  = red_s[half][0] + red_s[half][1] + red_s[half][2] + red_s[half][3];
        const float sums = red_ss[half][0] + red_ss[half][1] + red_ss[half][2] + red_ss[half][3];

        const float inv  = 1.0f / (float)FDIM;
        const float mean = sum * inv;
        const float var  = sums * inv - mean * mean;
        const float rstd = rsqrtf(var + 1e-5f);

        __half* mrow = mbuf + (size_t)r * FDIM;
#pragma unroll
        for (int i = 0; i < 3; i++) {
            const int f4 = t + i * 128;
            const int f  = f4 * 4;
            const float4 g = *(const float4*)(gamma + f);
            const float4 be = *(const float4*)(beta + f);
            const __half2 h01 = __floats2half2_rn((v[i].x - mean) * rstd * g.x + be.x,
                                                  (v[i].y - mean) * rstd * g.y + be.y);
            const __half2 h23 = __floats2half2_rn((v[i].z - mean) * rstd * g.z + be.z,
                                                  (v[i].w - mean) * rstd * g.w + be.w);
            uint2 pk;
            pk.x = *(const uint32_t*)&h01;
            pk.y = *(const uint32_t*)&h23;
            *(uint2*)(mrow + f) = pk;
        }
    }
}

// ---------------------------------------------------------------------------
// Kernel 2: fp16 mma.sync GEMM (proven R13/R15 core), 128x128x64, 256 thr,
// 2 CTAs/SM, all-cg cp.async, XOR row-parity swizzle.
// ---------------------------------------------------------------------------
#define BM 128
#define BN 128
#define BK 64
#define ROWH 64
#define A_TILE_B (BM * ROWH * 2)             // 16384 bytes
#define B_TILE_B (BN * ROWH * 2)             // 16384
#define STAGE_B (A_TILE_B + B_TILE_B)        // 32768
#define NSTAGE 3
#define NCHUNK (FDIM / BK)                   // 24
#define GEMM_SMEM (NSTAGE * STAGE_B)         // 98304

__global__ __launch_bounds__(256, 2) void gemm_mma_kernel(
    const __half* __restrict__ A,
    const __half* __restrict__ W,
    float* __restrict__ out)
{
    extern __shared__ __align__(16) char smc[];
    __half* sm = (__half*)smc;

    const int tid  = threadIdx.x;
    const int lane = tid & 31;
    const int wid  = tid >> 5;
    const int m0 = blockIdx.y * BM;
    const int n0 = blockIdx.x * BN;
    const int wm = (wid >> 2) * 64;          // 0, 64
    const int wn = (wid & 3) * 32;           // 0, 32, 64, 96

    const __half* gA = A + (size_t)m0 * FDIM;
    const __half* gB = W + (size_t)n0 * FDIM;

    const uint32_t smbase = smem_u32(sm);

    const int lrow = tid >> 1;
    const int lseg = (tid & 1) * 4;
    const uint32_t lxor = (uint32_t)(lrow & 1) << 6;

    auto load_chunk = [&](int chunk, int stage) {
        const uint32_t base = smbase + (uint32_t)stage * STAGE_B;
        const int koff = chunk * BK;
        const __half* pA = gA + (size_t)lrow * FDIM + koff;
        const uint32_t sA = base + (uint32_t)lrow * (ROWH * 2);
#pragma unroll
        for (int s = 0; s < 4; s++) {
            const uint32_t phys = ((uint32_t)(lseg + s) * 16) ^ lxor;
            CP_ASYNC16(sA + phys, pA + (lseg + s) * 8);
        }
        const __half* pB = gB + (size_t)lrow * FDIM + koff;
        const uint32_t sB = base + A_TILE_B + (uint32_t)lrow * (ROWH * 2);
#pragma unroll
        for (int s = 0; s < 4; s++) {
            const uint32_t phys = ((uint32_t)(lseg + s) * 16) ^ lxor;
            CP_ASYNC16(sB + phys, pB + (lseg + s) * 8);
        }
        CP_COMMIT();
    };

    float acc[4][4][4];
#pragma unroll
    for (int mt = 0; mt < 4; mt++)
#pragma unroll
        for (int nt = 0; nt < 4; nt++)
#pragma unroll
            for (int j = 0; j < 4; j++) acc[mt][nt][j] = 0.f;

    load_chunk(0, 0);
    load_chunk(1, 1);
    cp_wait<1>();
    __syncthreads();

    const int g2 = lane >> 2;                // 0..7
    const int cl = lane & 3;                 // k-quarter

    for (int i = 0; i < NCHUNK; i++) {
        const int ld = i + 2;
        if (ld < NCHUNK) load_chunk(ld, ld % NSTAGE);

        const int s = i % NSTAGE;
        const __half* As = sm + (size_t)s * (STAGE_B / 2);
        const __half* Bs = As + A_TILE_B / 2;

#pragma unroll
        for (int j = 0; j < 2; j++) {        // two 32-half subchunks
            const int fo = j * 32 + cl * 8;
            uint4 aLo[4], aHi[4];
#pragma unroll
            for (int mt = 0; mt < 4; mt++) {
                const int r = wm + mt * 16 + g2;
                const int xs = (r & 1) * 32;
                aLo[mt] = *(const uint4*)(As + r * ROWH + (fo ^ xs));
                aHi[mt] = *(const uint4*)(As + (r + 8) * ROWH + (fo ^ xs));
            }
            uint4 bv[4];
#pragma unroll
            for (int nt = 0; nt < 4; nt++) {
                const int n = wn + nt * 8 + g2;
                const int xs = (n & 1) * 32;
                bv[nt] = *(const uint4*)(Bs + n * ROWH + (fo ^ xs));
            }
#pragma unroll
            for (int nt = 0; nt < 4; nt++)
#pragma unroll
                for (int mt = 0; mt < 4; mt++)
                    mma_f16(acc[mt][nt], aLo[mt].x, aHi[mt].x, aLo[mt].y, aHi[mt].y,
                            bv[nt].x, bv[nt].y);
#pragma unroll
            for (int nt = 0; nt < 4; nt++)
#pragma unroll
                for (int mt = 0; mt < 4; mt++)
                    mma_f16(acc[mt][nt], aLo[mt].z, aHi[mt].z, aLo[mt].w, aHi[mt].w,
                            bv[nt].z, bv[nt].w);
        }

        if (ld < NCHUNK) { cp_wait<1>(); } else { cp_wait<0>(); }
        __syncthreads();
    }

    // epilogue: write with batch/row remap
    const int c2 = 2 * (lane & 3);
#pragma unroll
    for (int mt = 0; mt < 4; mt++) {
        const int mA = m0 + wm + mt * 16 + g2;
#pragma unroll
        for (int half = 0; half < 2; half++) {
            const int m  = mA + half * 8;
            const int b  = m / NPOS;
            const int nn = m - b * NPOS;
            float* orow = out + ((size_t)b * OUTROWS + 1 + nn) * ODIM + n0 + wn;
#pragma unroll
            for (int nt = 0; nt < 4; nt++) {
                float2 v;
                v.x = acc[mt][nt][2 * half + 0];
                v.y = acc[mt][nt][2 * half + 1];
                *(float2*)(orow + nt * 8 + c2) = v;
            }
        }
    }
}

// ---------------------------------------------------------------------------
extern "C" void kernel_launch(void* const* d_in, const int* in_sizes, int n_in,
                              void* d_out, int out_size)
{
    const float* x     = (const float*)d_in[0];
    const float* w_red = (const float*)d_in[1];
    const float* w_cvt = (const float*)d_in[2];
    const float* gamma = (const float*)d_in[3];
    const float* beta  = (const float*)d_in[4];
    float* out = (float*)d_out;

    __half* mbuf;
    __half* wred;
    cudaGetSymbolAddress((void**)&mbuf, g_mbuf);
    cudaGetSymbolAddress((void**)&wred, g_wred);

    cudaFuncSetAttribute(gemm_mma_kernel,
                         cudaFuncAttributeMaxDynamicSharedMemorySize, GEMM_SMEM);

    pre_kernel<<<PRE_BLOCKS, 256>>>(w_red, wred, x, w_cvt, gamma, beta, mbuf, out);
    gemm_mma_kernel<<<dim3(ODIM / BN, MROWS / BM), 256, GEMM_SMEM>>>(mbuf, wred, out);
}